// round 1
// baseline (speedup 1.0000x reference)
#include <cuda_runtime.h>

#define B_ 32
#define CIN 256
#define CC 64
#define HS 64
#define PS 4096         // 64*64
#define HT 14
#define PT 196          // 14*14
#define NG 32           // groups (2 channels per group)

// ---------------- device scratch (no allocations allowed) ----------------
__device__ float g_s_pre[B_*CC*PS];       // conv1x1(search) pre-GN
__device__ float g_corr[B_*CC*PS];        // global + local correlation
__device__ float g_y_pre[B_*CC*PS];       // conv3x3 pre-GN
__device__ float g_tglobal[B_*CC];        // mean of relu(gn(t)) per (b,c)
__device__ float g_tkernel[B_*CC*49];     // 7x7 pooled template kernel
__device__ float g_part_s[B_*NG*32*2];    // per-(b,g,tile) sum/sumsq for s
__device__ float g_part_y[B_*NG*16*2];    // per-(b,g,tile) sum/sumsq for y
__device__ float g_sc_s[B_*CC], g_sh_s[B_*CC];   // folded GN scale/shift for s
__device__ float g_sc_y[B_*CC], g_sh_y[B_*CC];   // folded GN scale/shift for y

// ---------------- kernel 1: template path, fully fused ----------------
// grid 64 (= b*2 + half), block 256. Each block: 32 output channels of one b.
// conv1x1 -> GN (groups are 2-channel, contained in half) -> relu ->
// t_global (spatial mean) + t_kernel (2x2 avg pool to 7x7).
__global__ void k_template(const float* __restrict__ tf, const float* __restrict__ wt,
                           const float* __restrict__ gw, const float* __restrict__ gb) {
    __shared__ float pre[32*PT];
    __shared__ float s_mean[16], s_rstd[16];
    int b = blockIdx.x >> 1;
    int o0 = (blockIdx.x & 1) * 32;
    int tid = threadIdx.x;

    if (tid < PT) {
        float acc[32];
#pragma unroll
        for (int o = 0; o < 32; o++) acc[o] = 0.f;
        const float* x = tf + (size_t)b*CIN*PT + tid;
        for (int c = 0; c < CIN; c++) {
            float xv = __ldg(x + c*PT);
#pragma unroll
            for (int o = 0; o < 32; o++)
                acc[o] = fmaf(__ldg(wt + (o0+o)*CIN + c), xv, acc[o]);
        }
#pragma unroll
        for (int o = 0; o < 32; o++) pre[o*PT + tid] = acc[o];
    }
    __syncthreads();

    int warp = tid >> 5, lane = tid & 31;
    for (int g = warp; g < 16; g += 8) {
        float s = 0.f, ss = 0.f;
        const float* base = pre + g*2*PT;
        for (int i = lane; i < 2*PT; i += 32) { float v = base[i]; s += v; ss += v*v; }
#pragma unroll
        for (int off = 16; off; off >>= 1) {
            s  += __shfl_down_sync(0xffffffffu, s,  off);
            ss += __shfl_down_sync(0xffffffffu, ss, off);
        }
        if (lane == 0) {
            float m = s / (float)(2*PT);
            float var = ss / (float)(2*PT) - m*m;
            s_mean[g] = m; s_rstd[g] = rsqrtf(var + 1e-5f);
        }
    }
    __syncthreads();

    for (int idx = tid; idx < 32*PT; idx += 256) {
        int c = idx / PT; int g = c >> 1;
        float v = fmaf((pre[idx] - s_mean[g]) * s_rstd[g], gw[o0+c], gb[o0+c]);
        pre[idx] = fmaxf(v, 0.f);
    }
    __syncthreads();

    for (int c = warp; c < 32; c += 8) {
        float s = 0.f;
        for (int i = lane; i < PT; i += 32) s += pre[c*PT + i];
#pragma unroll
        for (int off = 16; off; off >>= 1) s += __shfl_down_sync(0xffffffffu, s, off);
        if (lane == 0) g_tglobal[b*CC + o0 + c] = s * (1.f/(float)PT);
    }
    for (int idx = tid; idx < 32*49; idx += 256) {
        int c = idx / 49, k = idx % 49, kh = k / 7, kw = k % 7;
        const float* p = pre + c*PT + (2*kh)*HT + 2*kw;
        g_tkernel[(b*CC + o0 + c)*49 + k] = 0.25f*(p[0] + p[1] + p[HT] + p[HT+1]);
    }
}

// ---------------- kernel 2: conv1x1 search (tiled GEMM) + GN partials ----------------
// grid (32 tiles, 32 b), block 256. Per block: C[64 out][128 pos], K=256.
__global__ void k_search(const float* __restrict__ sf, const float* __restrict__ ws) {
    __shared__ float As[CC*32];    // [o][kk]
    __shared__ float Bs[32*128];   // [kk][j]
    int tile = blockIdx.x, b = blockIdx.y;
    int tid = threadIdx.x;
    int tx = tid & 31, ty = tid >> 5;
    float acc[8][4];
#pragma unroll
    for (int i = 0; i < 8; i++)
#pragma unroll
        for (int j = 0; j < 4; j++) acc[i][j] = 0.f;

    for (int k0 = 0; k0 < CIN; k0 += 32) {
        __syncthreads();
        for (int idx = tid; idx < CC*32; idx += 256) {
            int o = idx >> 5, kk = idx & 31;
            As[idx] = ws[o*CIN + k0 + kk];
        }
        for (int idx = tid; idx < 32*128; idx += 256) {
            int kk = idx >> 7, j = idx & 127;
            Bs[idx] = sf[((size_t)b*CIN + k0 + kk)*PS + tile*128 + j];
        }
        __syncthreads();
#pragma unroll
        for (int kk = 0; kk < 32; kk++) {
            float bv[4];
#pragma unroll
            for (int j = 0; j < 4; j++) bv[j] = Bs[kk*128 + tx*4 + j];
#pragma unroll
            for (int i = 0; i < 8; i++) {
                float a = As[(ty*8 + i)*32 + kk];
#pragma unroll
                for (int j = 0; j < 4; j++) acc[i][j] = fmaf(a, bv[j], acc[i][j]);
            }
        }
    }

    // write + per-group partial stats (warp ty owns groups ty*4 .. ty*4+3)
    float gs[4], gss[4];
#pragma unroll
    for (int q = 0; q < 4; q++) { gs[q] = 0.f; gss[q] = 0.f; }
#pragma unroll
    for (int i = 0; i < 8; i++) {
        int o = ty*8 + i;
        float4 v = make_float4(acc[i][0], acc[i][1], acc[i][2], acc[i][3]);
        *(float4*)&g_s_pre[((size_t)b*CC + o)*PS + tile*128 + tx*4] = v;
        int q = i >> 1;
#pragma unroll
        for (int j = 0; j < 4; j++) { gs[q] += acc[i][j]; gss[q] += acc[i][j]*acc[i][j]; }
    }
#pragma unroll
    for (int q = 0; q < 4; q++) {
#pragma unroll
        for (int off = 16; off; off >>= 1) {
            gs[q]  += __shfl_down_sync(0xffffffffu, gs[q],  off);
            gss[q] += __shfl_down_sync(0xffffffffu, gss[q], off);
        }
    }
    if (tx == 0) {
#pragma unroll
        for (int q = 0; q < 4; q++) {
            int g = ty*4 + q;
            g_part_s[((b*NG + g)*32 + tile)*2 + 0] = gs[q];
            g_part_s[((b*NG + g)*32 + tile)*2 + 1] = gss[q];
        }
    }
}

// ---------------- kernel 3: fold GN stats into per-channel scale/shift ----------------
__global__ void k_stats(int which, int ntiles, float inv_n,
                        const float* __restrict__ gw, const float* __restrict__ gb) {
    int i = blockIdx.x * blockDim.x + threadIdx.x;
    if (i >= B_*CC) return;
    int b = i >> 6, c = i & 63, g = c >> 1;
    const float* part = which ? g_part_y : g_part_s;
    float* sc = which ? g_sc_y : g_sc_s;
    float* sh = which ? g_sh_y : g_sh_s;
    float s = 0.f, ss = 0.f;
    const float* p = part + (size_t)(b*NG + g)*ntiles*2;
    for (int t = 0; t < ntiles; t++) { s += p[2*t]; ss += p[2*t + 1]; }
    float m = s * inv_n;
    float var = ss * inv_n - m*m;
    float r = rsqrtf(var + 1e-5f);
    float scale = r * gw[c];
    sc[i] = scale;
    sh[i] = gb[c] - m*scale;
}

// ---------------- kernel 4: global + local (depthwise 7x7) correlation ----------------
// grid 2048 (b*64+c), block 256. GN-apply + relu fused into the halo load.
__global__ void k_corr() {
    __shared__ float tile[70*70];
    __shared__ float tk[49];
    int bc = blockIdx.x;
    int tid = threadIdx.x;
    float sc = g_sc_s[bc], sh = g_sh_s[bc], tg = g_tglobal[bc];
    if (tid < 49) tk[tid] = g_tkernel[bc*49 + tid];
    const float* sp = g_s_pre + (size_t)bc*PS;
    for (int idx = tid; idx < 4900; idx += 256) {
        int r = idx / 70 - 3, c = idx % 70 - 3;
        float v = 0.f;
        if ((unsigned)r < 64u && (unsigned)c < 64u)
            v = fmaxf(fmaf(sp[r*64 + c], sc, sh), 0.f);
        tile[idx] = v;
    }
    __syncthreads();
    float* dst = g_corr + (size_t)bc*PS;
#pragma unroll
    for (int q = 0; q < 4; q++) {
        int qi = tid + q*256;            // 0..1023 quads
        int y = qi >> 4, x4 = (qi & 15) << 2;
        float a[4];
        const float* ctr = tile + (y+3)*70 + (x4+3);
#pragma unroll
        for (int j = 0; j < 4; j++) a[j] = ctr[j] * tg;
#pragma unroll
        for (int kh = 0; kh < 7; kh++) {
            const float* row = tile + (y+kh)*70 + x4;
            float rv[10];
#pragma unroll
            for (int t = 0; t < 10; t++) rv[t] = row[t];
#pragma unroll
            for (int kw = 0; kw < 7; kw++) {
                float w = tk[kh*7 + kw];
#pragma unroll
                for (int j = 0; j < 4; j++) a[j] = fmaf(w, rv[kw + j], a[j]);
            }
        }
        float4 v = make_float4(a[0], a[1], a[2], a[3]);
        *(float4*)&dst[y*64 + x4] = v;
    }
}

// ---------------- kernel 5: conv3x3 (implicit GEMM, smem tiled) + GN partials ----------------
// grid (16 tiles, 4 oblk, 32 b), block 256.
// Block: 16 out-ch x 16x16 positions. Thread: 4 o x 4 consecutive x.
__global__ void k_conv3(const float* __restrict__ wp1) {
    __shared__ float xs[8*324];       // 8 in-ch x 18x18 halo tile
    __shared__ float wsm[16*8*9];     // 16 o x 8 c x 9
    __shared__ float s_red[8][4];
    int tile = blockIdx.x, oblk = blockIdx.y, b = blockIdx.z;
    int ty0 = (tile >> 2) << 4, tx0 = (tile & 3) << 4;
    int tid = threadIdx.x;
    int oq = tid >> 6;                 // 0..3 (constant within a warp)
    int quad = tid & 63;
    int py = quad >> 2, px4 = (quad & 3) << 2;

    float acc[4][4];
#pragma unroll
    for (int i = 0; i < 4; i++)
#pragma unroll
        for (int j = 0; j < 4; j++) acc[i][j] = 0.f;

    for (int c0 = 0; c0 < CC; c0 += 8) {
        __syncthreads();
        for (int idx = tid; idx < 2592; idx += 256) {
            int cc = idx / 324, rem = idx - cc*324;
            int rr = rem / 18, col = rem - rr*18;
            int gy = ty0 + rr - 1, gx = tx0 + col - 1;
            float v = 0.f;
            if ((unsigned)gy < 64u && (unsigned)gx < 64u)
                v = g_corr[((size_t)b*CC + c0 + cc)*PS + gy*64 + gx];
            xs[idx] = v;
        }
        for (int idx = tid; idx < 1152; idx += 256) {
            int o = idx / 72, rem = idx - o*72;
            wsm[idx] = wp1[(((size_t)(oblk*16 + o))*CC + c0)*9 + rem];
        }
        __syncthreads();
#pragma unroll
        for (int cc = 0; cc < 8; cc++) {
            const float* base = xs + cc*324 + py*18 + px4;
            float xv[18];
#pragma unroll
            for (int r = 0; r < 3; r++)
#pragma unroll
                for (int s = 0; s < 6; s++) xv[r*6 + s] = base[r*18 + s];
#pragma unroll
            for (int i = 0; i < 4; i++) {
                const float* w9 = wsm + ((oq*4 + i)*8 + cc)*9;
                float w[9];
#pragma unroll
                for (int k = 0; k < 9; k++) w[k] = w9[k];
#pragma unroll
                for (int r = 0; r < 3; r++)
#pragma unroll
                    for (int t = 0; t < 3; t++)
#pragma unroll
                        for (int j = 0; j < 4; j++)
                            acc[i][j] = fmaf(w[r*3 + t], xv[r*6 + j + t], acc[i][j]);
            }
        }
    }

#pragma unroll
    for (int i = 0; i < 4; i++) {
        int o = oblk*16 + oq*4 + i;
        float4 v = make_float4(acc[i][0], acc[i][1], acc[i][2], acc[i][3]);
        *(float4*)&g_y_pre[((size_t)b*CC + o)*PS + (ty0+py)*64 + tx0 + px4] = v;
    }

    // GN partials: thread owns 2 local groups (channels oq*4..+3 -> groups oq*2, oq*2+1)
    float ps[2] = {0.f, 0.f}, pss[2] = {0.f, 0.f};
#pragma unroll
    for (int i = 0; i < 4; i++) {
        int gi = i >> 1;
#pragma unroll
        for (int j = 0; j < 4; j++) { float v = acc[i][j]; ps[gi] += v; pss[gi] += v*v; }
    }
#pragma unroll
    for (int gi = 0; gi < 2; gi++)
#pragma unroll
        for (int off = 16; off; off >>= 1) {
            ps[gi]  += __shfl_down_sync(0xffffffffu, ps[gi],  off);
            pss[gi] += __shfl_down_sync(0xffffffffu, pss[gi], off);
        }
    int warp = tid >> 5, lane = tid & 31;
    if (lane == 0) {
        s_red[warp][0] = ps[0]; s_red[warp][1] = pss[0];
        s_red[warp][2] = ps[1]; s_red[warp][3] = pss[1];
    }
    __syncthreads();
    if (tid < 16) {
        int gidx = tid >> 1, isq = tid & 1;   // local group 0..7
        int oqq = gidx >> 1, gi = gidx & 1;
        float s = s_red[oqq*2][gi*2 + isq] + s_red[oqq*2 + 1][gi*2 + isq];
        g_part_y[((b*NG + oblk*8 + gidx)*16 + tile)*2 + isq] = s;
    }
}

// ---------------- kernel 6: GN-apply + relu + final 1x1 + bias ----------------
__global__ void k_out(const float* __restrict__ wp2, const float* __restrict__ bp2,
                      float* __restrict__ out) {
    int i = blockIdx.x*256 + threadIdx.x;     // 0..131071
    int b = i >> 12, p = i & 4095;
    float acc = bp2[0];
    const float* yp = g_y_pre + (size_t)(b*CC)*PS + p;
#pragma unroll 8
    for (int o = 0; o < 64; o++) {
        int bc = b*CC + o;
        float v = fmaxf(fmaf(yp[(size_t)o*PS], g_sc_y[bc], g_sh_y[bc]), 0.f);
        acc = fmaf(wp2[o], v, acc);
    }
    out[i] = acc;
}

// ---------------- launch ----------------
extern "C" void kernel_launch(void* const* d_in, const int* in_sizes, int n_in,
                              void* d_out, int out_size) {
    const float* tf  = (const float*)d_in[0];   // template_feat [32,256,14,14]
    const float* sf  = (const float*)d_in[1];   // search_feat   [32,256,64,64]
    const float* wt  = (const float*)d_in[2];   // w_t  [64,256]
    const float* gtw = (const float*)d_in[3];
    const float* gtb = (const float*)d_in[4];
    const float* ws  = (const float*)d_in[5];   // w_s  [64,256]
    const float* gsw = (const float*)d_in[6];
    const float* gsb = (const float*)d_in[7];
    const float* wp1 = (const float*)d_in[8];   // w_p1 [64,64,3,3]
    const float* gpw = (const float*)d_in[9];
    const float* gpb = (const float*)d_in[10];
    const float* wp2 = (const float*)d_in[11];  // w_p2 [1,64]
    const float* bp2 = (const float*)d_in[12];  // b_p2 [1]
    float* out = (float*)d_out;

    k_template<<<64, 256>>>(tf, wt, gtw, gtb);
    k_search<<<dim3(32, 32), 256>>>(sf, ws);
    k_stats<<<8, 256>>>(0, 32, 1.f/8192.f, gsw, gsb);
    k_corr<<<2048, 256>>>();
    k_conv3<<<dim3(16, 4, 32), 256>>>(wp1);
    k_stats<<<8, 256>>>(1, 16, 1.f/8192.f, gpw, gpb);
    k_out<<<512, 256>>>(wp2, bp2, out);
}